// round 1
// baseline (speedup 1.0000x reference)
#include <cuda_runtime.h>
#include <cstdint>

// ---------------------------------------------------------------------------
// SAGEConvolution: out = agg(h @ W2_l) + h @ W2_r + b2,
//                  h   = relu(agg(x @ W1_l) + x @ W1_r + b1)
// where agg(u)[i] = inv_deg[i] * sum_{e: dst[e]==i} u[src[e]]
// (projection-first form: agg(x)@W == agg(x@W) by linearity)
// ---------------------------------------------------------------------------

#define N_NODES   100000
#define N_EDGES_M 1600000
#define SCAN_B    1024
#define NB_MAX    128

// ---- scratch (device globals; no allocation allowed) ----
__device__ float g_UV[(size_t)N_NODES * 256];   // [u | v] after GEMM1
__device__ float g_H [(size_t)N_NODES * 128];   // hidden
__device__ float g_PQ[(size_t)N_NODES * 128];   // [p | q] after GEMM2
__device__ int   g_deg[N_NODES];
__device__ int   g_cur[N_NODES];
__device__ int   g_rowptr[N_NODES + 1];
__device__ int   g_bsum[NB_MAX];
__device__ int   g_boff[NB_MAX];
__device__ float g_invdeg[N_NODES];
__device__ int   g_col[N_EDGES_M];
__device__ int   g_e32[2 * N_EDGES_M];
__device__ int   g_flag;                        // 1 => edge buffer is int32
__device__ float g_B1[128 * 256];
__device__ float g_B2[128 * 128];
__device__ float g_bias1[256];
__device__ float g_bias2[128];

// ---- setup kernels --------------------------------------------------------

__global__ void k_zero(int n) {
    int i = blockIdx.x * blockDim.x + threadIdx.x;
    if (i < n) { g_deg[i] = 0; g_cur[i] = 0; }
    if (i == 0) g_flag = 0;
}

// If edge_index is int64, every odd 32-bit word (high half) is 0.
// If any odd word is nonzero, the buffer is int32.
__global__ void k_detect(const unsigned int* __restrict__ w) {
    int i = blockIdx.x * blockDim.x + threadIdx.x;
    if (i < 4096 && w[2 * i + 1] != 0u) g_flag = 1;
}

__global__ void k_convert(const void* __restrict__ ep, int twoE) {
    int i = blockIdx.x * blockDim.x + threadIdx.x;
    if (i >= twoE) return;
    if (g_flag) g_e32[i] = ((const int*)ep)[i];
    else        g_e32[i] = (int)(((const long long*)ep)[i]);
}

__global__ void k_hist(int E) {
    int i = blockIdx.x * blockDim.x + threadIdx.x;
    if (i < E) atomicAdd(&g_deg[g_e32[E + i]], 1);
}

__global__ void k_scan1(int n) {   // per-block inclusive scan of deg -> rowptr
    __shared__ int sm[SCAN_B];
    int tid = threadIdx.x;
    int i = blockIdx.x * SCAN_B + tid;
    int v = (i < n) ? g_deg[i] : 0;
    sm[tid] = v;
    __syncthreads();
    for (int off = 1; off < SCAN_B; off <<= 1) {
        int t = (tid >= off) ? sm[tid - off] : 0;
        __syncthreads();
        sm[tid] += t;
        __syncthreads();
    }
    if (i < n) g_rowptr[i] = sm[tid];
    if (tid == SCAN_B - 1) g_bsum[blockIdx.x] = sm[tid];
}

__global__ void k_scan2(int nb) {  // exclusive scan of block sums (nb <= 128)
    __shared__ int sm[128];
    int tid = threadIdx.x;
    int v = (tid < nb) ? g_bsum[tid] : 0;
    sm[tid] = v;
    __syncthreads();
    for (int off = 1; off < 128; off <<= 1) {
        int t = (tid >= off) ? sm[tid - off] : 0;
        __syncthreads();
        sm[tid] += t;
        __syncthreads();
    }
    g_boff[tid] = sm[tid] - v;
}

__global__ void k_scan3(int n, int E) {   // inclusive -> exclusive + inv_deg
    int i = blockIdx.x * blockDim.x + threadIdx.x;
    if (i >= n) return;
    int d = g_deg[i];
    int ex = g_rowptr[i] - d + g_boff[i >> 10];
    g_rowptr[i] = ex;
    g_invdeg[i] = 1.0f / (float)max(d, 1);
    if (i == n - 1) g_rowptr[n] = E;
}

__global__ void k_fill(int E) {
    int i = blockIdx.x * blockDim.x + threadIdx.x;
    if (i >= E) return;
    int d = g_e32[E + i];
    int pos = atomicAdd(&g_cur[d], 1);
    g_col[g_rowptr[d] + pos] = g_e32[i];
}

// Build concatenated weight [Wl | Wr] (K x (Nl+Nr)) and bias [0.. | b]
__global__ void k_concat(const float* __restrict__ Wl, const float* __restrict__ Wr,
                         const float* __restrict__ b,
                         float* __restrict__ B, float* __restrict__ bias,
                         int K, int Nl, int Nr) {
    int nn = Nl + Nr;
    int i = blockIdx.x * blockDim.x + threadIdx.x;
    if (i < K * nn) {
        int r = i / nn, c = i % nn;
        B[i] = (c < Nl) ? Wl[r * Nl + c] : Wr[r * Nr + (c - Nl)];
    }
    if (i < nn) bias[i] = (i < Nl) ? 0.0f : b[i - Nl];
}

// ---- SGEMM: C[M x N] = A[M x 128] * B[128 x N] + bias[N]  (fp32, FFMA2) ----
// BM=128, BN=64, BK=16, 128 threads, 8x8 per-thread tile, accumulators packed
// along M in f32x2 pairs; FMA via PTX fma.rn.f32x2 (2x fp32 rate on sm_103a).
__global__ void __launch_bounds__(128)
k_sgemm(const float* __restrict__ A, const float* __restrict__ B,
        const float* __restrict__ bias, float* __restrict__ C, int M, int N) {
    const int K = 128;
    __shared__ __align__(16) float As[16][128];
    __shared__ __align__(16) float Bs[16][64];

    int tid  = threadIdx.x;
    int row0 = blockIdx.x * 128;
    int col0 = blockIdx.y * 64;
    int tx = tid & 7;     // 0..7   (N: 8 cols each)
    int ty = tid >> 3;    // 0..15  (M: 8 rows each, as 4 f32x2 pairs)

    unsigned long long acc[4][8];
#pragma unroll
    for (int i = 0; i < 4; i++)
#pragma unroll
        for (int j = 0; j < 8; j++) acc[i][j] = 0ull;

    int arow = row0 + tid;
    bool avalid = arow < M;
    const float* Arow = A + (size_t)arow * K;
    int kb = tid >> 4;             // 0..7
    int nn = (tid & 15) * 4;       // 0..60

    for (int k0 = 0; k0 < K; k0 += 16) {
        // A tile (transposed into As[k][m]) — each thread loads one A row chunk
#pragma unroll
        for (int i = 0; i < 4; i++) {
            float4 v = avalid ? *(const float4*)(Arow + k0 + i * 4)
                              : make_float4(0.f, 0.f, 0.f, 0.f);
            As[i * 4 + 0][tid] = v.x;
            As[i * 4 + 1][tid] = v.y;
            As[i * 4 + 2][tid] = v.z;
            As[i * 4 + 3][tid] = v.w;
        }
        // B tile
#pragma unroll
        for (int i = 0; i < 2; i++) {
            float4 v = *(const float4*)(B + (size_t)(k0 + kb + 8 * i) * N + col0 + nn);
            *(float4*)&Bs[kb + 8 * i][nn] = v;
        }
        __syncthreads();

#pragma unroll
        for (int kk = 0; kk < 16; kk++) {
            unsigned long long a2[4];
#pragma unroll
            for (int i = 0; i < 4; i++)
                a2[i] = *(const unsigned long long*)&As[kk][ty * 8 + i * 2];
            float bv[8];
            *(float4*)&bv[0] = *(const float4*)&Bs[kk][tx * 8];
            *(float4*)&bv[4] = *(const float4*)&Bs[kk][tx * 8 + 4];
#pragma unroll
            for (int j = 0; j < 8; j++) {
                unsigned long long bb;
                asm("mov.b64 %0, {%1, %1};" : "=l"(bb) : "r"(__float_as_uint(bv[j])));
#pragma unroll
                for (int i = 0; i < 4; i++)
                    asm("fma.rn.f32x2 %0, %1, %2, %0;"
                        : "+l"(acc[i][j]) : "l"(a2[i]), "l"(bb));
            }
        }
        __syncthreads();
    }

    // epilogue: unpack pairs (lo = row, hi = row+1), add bias
#pragma unroll
    for (int i = 0; i < 4; i++) {
        int r0 = row0 + ty * 8 + i * 2;
#pragma unroll
        for (int j = 0; j < 8; j++) {
            int c = col0 + tx * 8 + j;
            float lo = __uint_as_float((unsigned)(acc[i][j] & 0xffffffffull));
            float hi = __uint_as_float((unsigned)(acc[i][j] >> 32));
            float bs = bias[c];
            if (r0 < M)     C[(size_t)r0 * N + c]       = lo + bs;
            if (r0 + 1 < M) C[(size_t)(r0 + 1) * N + c] = hi + bs;
        }
    }
}

// ---- aggregation: O[i] = act(inv_deg[i] * sum_nbr U[src] + V[i]) -----------
// One warp per destination node. VEC = DIM/32 floats per lane (4 or 2).
template <int VEC, bool RELU>
__global__ void k_agg(const float* __restrict__ U, int ldu,
                      const float* __restrict__ V, int ldv,
                      float* __restrict__ O, int ldo, int n) {
    int warp = blockIdx.x * (blockDim.x >> 5) + (threadIdx.x >> 5);
    int lane = threadIdx.x & 31;
    if (warp >= n) return;
    int beg = g_rowptr[warp], end = g_rowptr[warp + 1];
    const float* Ub = U + lane * VEC;
    float id = g_invdeg[warp];

    if constexpr (VEC == 4) {
        float4 a = make_float4(0.f, 0.f, 0.f, 0.f);
        int e = beg;
        for (; e + 2 <= end; e += 2) {
            int s0 = g_col[e], s1 = g_col[e + 1];
            float4 v0 = *(const float4*)(Ub + (size_t)s0 * ldu);
            float4 v1 = *(const float4*)(Ub + (size_t)s1 * ldu);
            a.x += v0.x + v1.x; a.y += v0.y + v1.y;
            a.z += v0.z + v1.z; a.w += v0.w + v1.w;
        }
        if (e < end) {
            int s = g_col[e];
            float4 v = *(const float4*)(Ub + (size_t)s * ldu);
            a.x += v.x; a.y += v.y; a.z += v.z; a.w += v.w;
        }
        float4 vv = *(const float4*)(V + (size_t)warp * ldv + lane * 4);
        float4 o;
        o.x = a.x * id + vv.x; o.y = a.y * id + vv.y;
        o.z = a.z * id + vv.z; o.w = a.w * id + vv.w;
        if (RELU) {
            o.x = fmaxf(o.x, 0.f); o.y = fmaxf(o.y, 0.f);
            o.z = fmaxf(o.z, 0.f); o.w = fmaxf(o.w, 0.f);
        }
        *(float4*)(O + (size_t)warp * ldo + lane * 4) = o;
    } else {
        float2 a = make_float2(0.f, 0.f);
        int e = beg;
        for (; e + 2 <= end; e += 2) {
            int s0 = g_col[e], s1 = g_col[e + 1];
            float2 v0 = *(const float2*)(Ub + (size_t)s0 * ldu);
            float2 v1 = *(const float2*)(Ub + (size_t)s1 * ldu);
            a.x += v0.x + v1.x; a.y += v0.y + v1.y;
        }
        if (e < end) {
            int s = g_col[e];
            float2 v = *(const float2*)(Ub + (size_t)s * ldu);
            a.x += v.x; a.y += v.y;
        }
        float2 vv = *(const float2*)(V + (size_t)warp * ldv + lane * 2);
        float2 o;
        o.x = a.x * id + vv.x; o.y = a.y * id + vv.y;
        if (RELU) { o.x = fmaxf(o.x, 0.f); o.y = fmaxf(o.y, 0.f); }
        *(float2*)(O + (size_t)warp * ldo + lane * 2) = o;
    }
}

// ---- launch ----------------------------------------------------------------

extern "C" void kernel_launch(void* const* d_in, const int* in_sizes, int n_in,
                              void* d_out, int out_size) {
    const float* x   = (const float*)d_in[0];
    const void*  edg = d_in[1];
    const float* W1l = (const float*)d_in[2];
    const float* b1  = (const float*)d_in[3];
    const float* W1r = (const float*)d_in[4];
    const float* W2l = (const float*)d_in[5];
    const float* b2  = (const float*)d_in[6];
    const float* W2r = (const float*)d_in[7];

    int n    = in_sizes[0] / 128;   // 100000
    int twoE = in_sizes[1];         // 3,200,000
    int E    = twoE / 2;

    float *UV, *H, *PQ, *B1, *B2, *bs1, *bs2;
    cudaGetSymbolAddress((void**)&UV,  g_UV);
    cudaGetSymbolAddress((void**)&H,   g_H);
    cudaGetSymbolAddress((void**)&PQ,  g_PQ);
    cudaGetSymbolAddress((void**)&B1,  g_B1);
    cudaGetSymbolAddress((void**)&B2,  g_B2);
    cudaGetSymbolAddress((void**)&bs1, g_bias1);
    cudaGetSymbolAddress((void**)&bs2, g_bias2);

    // CSR build
    k_zero<<<(n + 255) / 256, 256>>>(n);
    k_detect<<<16, 256>>>((const unsigned int*)edg);
    k_convert<<<(twoE + 255) / 256, 256>>>(edg, twoE);
    k_hist<<<(E + 255) / 256, 256>>>(E);
    int nb = (n + SCAN_B - 1) / SCAN_B;
    k_scan1<<<nb, SCAN_B>>>(n);
    k_scan2<<<1, 128>>>(nb);
    k_scan3<<<(n + 255) / 256, 256>>>(n, E);
    k_fill<<<(E + 255) / 256, 256>>>(E);

    // weight concat + bias
    k_concat<<<(128 * 256 + 255) / 256, 256>>>(W1l, W1r, b1, B1, bs1, 128, 128, 128);
    k_concat<<<(128 * 128 + 255) / 256, 256>>>(W2l, W2r, b2, B2, bs2, 128, 64, 64);

    // layer 1: [u|v] = x @ [W1l|W1r] (+b1 on v);  h = relu(agg(u)*invdeg + v)
    dim3 g1((n + 127) / 128, 4);
    k_sgemm<<<g1, 128>>>(x, B1, bs1, UV, n, 256);
    k_agg<4, true><<<(n + 7) / 8, 256>>>(UV, 256, UV + 128, 256, H, 128, n);

    // layer 2: [p|q] = h @ [W2l|W2r] (+b2 on q);  out = agg(p)*invdeg + q
    dim3 g2((n + 127) / 128, 2);
    k_sgemm<<<g2, 128>>>(H, B2, bs2, PQ, n, 128);
    k_agg<2, false><<<(n + 7) / 8, 256>>>(PQ, 128, PQ + 64, 128, (float*)d_out, 64, n);
}

// round 3
// speedup vs baseline: 1.7257x; 1.7257x over previous
#include <cuda_runtime.h>
#include <cuda_bf16.h>
#include <cstdint>

// ---------------------------------------------------------------------------
// SAGEConvolution via projection-first form:
//   h   = relu(agg(x @ W1_l) + x @ W1_r + b1)
//   out = agg(h @ W2_l) + h @ W2_r + b2
// GEMMs: warp-level bf16 mma.sync (HMMA) with 2-term error-compensated split
//   D = Ah*Bh + Al*Bh + Ah*Bl   (fp32 accumulate; dropped Al*Bl ~ 2^-18)
// agg via CSR gather-sum (one warp per destination node).
// ---------------------------------------------------------------------------

#define N_NODES   100000
#define N_EDGES_M 1600000
#define SCAN_B    1024
#define NB_MAX    128
#define SM_STRIDE 136   // bf16 elements per smem row (128 + 8 pad)

// ---- scratch (device globals; no allocation allowed) ----
__device__ float g_UV[(size_t)N_NODES * 256];   // [u | v] after GEMM1
__device__ float g_PQ[(size_t)N_NODES * 128];   // [p | q] after GEMM2
__device__ __nv_bfloat16 g_Xh[(size_t)N_NODES * 128];
__device__ __nv_bfloat16 g_Xl[(size_t)N_NODES * 128];
__device__ __nv_bfloat16 g_Hh[(size_t)N_NODES * 128];
__device__ __nv_bfloat16 g_Hl[(size_t)N_NODES * 128];
__device__ int   g_deg[N_NODES];
__device__ int   g_cur[N_NODES];
__device__ int   g_rowptr[N_NODES + 1];
__device__ int   g_bsum[NB_MAX];
__device__ int   g_boff[NB_MAX];
__device__ float g_invdeg[N_NODES];
__device__ int   g_col[N_EDGES_M];
__device__ int   g_e32[2 * N_EDGES_M];
__device__ int   g_flag;                        // 1 => edge buffer is int32
__device__ __nv_bfloat16 g_B1h[256 * 128];
__device__ __nv_bfloat16 g_B1l[256 * 128];
__device__ __nv_bfloat16 g_B2h[128 * 128];
__device__ __nv_bfloat16 g_B2l[128 * 128];
__device__ float g_bias1[256];
__device__ float g_bias2[128];

// ============================ helpers =======================================

__device__ __forceinline__ uint32_t smem_u32(const void* p) {
    uint32_t a;
    asm("{ .reg .u64 t; cvta.to.shared.u64 t, %1; cvt.u32.u64 %0, t; }"
        : "=r"(a) : "l"(p));
    return a;
}

__device__ __forceinline__ void ldsm_x4(uint32_t addr, uint32_t& r0, uint32_t& r1,
                                        uint32_t& r2, uint32_t& r3) {
    asm volatile("ldmatrix.sync.aligned.m8n8.x4.shared.b16 {%0,%1,%2,%3}, [%4];"
                 : "=r"(r0), "=r"(r1), "=r"(r2), "=r"(r3) : "r"(addr));
}

__device__ __forceinline__ void mma_bf16(float* c, const uint32_t* a,
                                         uint32_t b0, uint32_t b1) {
    asm volatile(
        "mma.sync.aligned.m16n8k16.row.col.f32.bf16.bf16.f32 "
        "{%0,%1,%2,%3}, {%4,%5,%6,%7}, {%8,%9}, {%0,%1,%2,%3};"
        : "+f"(c[0]), "+f"(c[1]), "+f"(c[2]), "+f"(c[3])
        : "r"(a[0]), "r"(a[1]), "r"(a[2]), "r"(a[3]), "r"(b0), "r"(b1));
}

__device__ __forceinline__ void split4(float4 v, uint2& hv, uint2& lv) {
    __nv_bfloat162 h01 = __float22bfloat162_rn(make_float2(v.x, v.y));
    __nv_bfloat162 h23 = __float22bfloat162_rn(make_float2(v.z, v.w));
    float2 f01 = __bfloat1622float2(h01);
    float2 f23 = __bfloat1622float2(h23);
    __nv_bfloat162 l01 = __float22bfloat162_rn(make_float2(v.x - f01.x, v.y - f01.y));
    __nv_bfloat162 l23 = __float22bfloat162_rn(make_float2(v.z - f23.x, v.w - f23.y));
    hv.x = *(uint32_t*)&h01; hv.y = *(uint32_t*)&h23;
    lv.x = *(uint32_t*)&l01; lv.y = *(uint32_t*)&l23;
}

// ---- setup kernels --------------------------------------------------------

__global__ void k_zero(int n) {
    int i = blockIdx.x * blockDim.x + threadIdx.x;
    if (i < n) { g_deg[i] = 0; g_cur[i] = 0; }
    if (i == 0) g_flag = 0;
}

__global__ void k_detect(const unsigned int* __restrict__ w) {
    int i = blockIdx.x * blockDim.x + threadIdx.x;
    if (i < 4096 && w[2 * i + 1] != 0u) g_flag = 1;
}

__global__ void k_convert(const void* __restrict__ ep, int twoE) {
    int i = blockIdx.x * blockDim.x + threadIdx.x;
    if (i >= twoE) return;
    if (g_flag) g_e32[i] = ((const int*)ep)[i];
    else        g_e32[i] = (int)(((const long long*)ep)[i]);
}

__global__ void k_hist(int E) {
    int i = blockIdx.x * blockDim.x + threadIdx.x;
    if (i < E) atomicAdd(&g_deg[g_e32[E + i]], 1);
}

__global__ void k_scan1(int n) {
    __shared__ int sm[SCAN_B];
    int tid = threadIdx.x;
    int i = blockIdx.x * SCAN_B + tid;
    int v = (i < n) ? g_deg[i] : 0;
    sm[tid] = v;
    __syncthreads();
    for (int off = 1; off < SCAN_B; off <<= 1) {
        int t = (tid >= off) ? sm[tid - off] : 0;
        __syncthreads();
        sm[tid] += t;
        __syncthreads();
    }
    if (i < n) g_rowptr[i] = sm[tid];
    if (tid == SCAN_B - 1) g_bsum[blockIdx.x] = sm[tid];
}

__global__ void k_scan2(int nb) {
    __shared__ int sm[128];
    int tid = threadIdx.x;
    int v = (tid < nb) ? g_bsum[tid] : 0;
    sm[tid] = v;
    __syncthreads();
    for (int off = 1; off < 128; off <<= 1) {
        int t = (tid >= off) ? sm[tid - off] : 0;
        __syncthreads();
        sm[tid] += t;
        __syncthreads();
    }
    g_boff[tid] = sm[tid] - v;
}

__global__ void k_scan3(int n, int E) {
    int i = blockIdx.x * blockDim.x + threadIdx.x;
    if (i >= n) return;
    int d = g_deg[i];
    int ex = g_rowptr[i] - d + g_boff[i >> 10];
    g_rowptr[i] = ex;
    g_invdeg[i] = 1.0f / (float)max(d, 1);
    if (i == n - 1) g_rowptr[n] = E;
}

__global__ void k_fill(int E) {
    int i = blockIdx.x * blockDim.x + threadIdx.x;
    if (i >= E) return;
    int d = g_e32[E + i];
    int pos = atomicAdd(&g_cur[d], 1);
    g_col[g_rowptr[d] + pos] = g_e32[i];
}

// split x (fp32) into bf16 hi/lo
__global__ void k_prepA(const float* __restrict__ X,
                        __nv_bfloat16* __restrict__ Ah,
                        __nv_bfloat16* __restrict__ Al, int total4) {
    int i = blockIdx.x * blockDim.x + threadIdx.x;
    if (i >= total4) return;
    float4 v = __ldg((const float4*)X + i);
    uint2 hv, lv;
    split4(v, hv, lv);
    *(uint2*)(Ah + (size_t)i * 4) = hv;
    *(uint2*)(Al + (size_t)i * 4) = lv;
}

// Build split-bf16 B = [Wl | Wr]^T as [N][K] rows, and bias [0.. | b]
__global__ void k_prepB(const float* __restrict__ Wl, const float* __restrict__ Wr,
                        const float* __restrict__ b,
                        __nv_bfloat16* __restrict__ Bh, __nv_bfloat16* __restrict__ Bl,
                        float* __restrict__ bias, int K, int Nl, int Nr) {
    int N = Nl + Nr;
    int i = blockIdx.x * blockDim.x + threadIdx.x;
    if (i < N * K) {
        int nrow = i / K, k = i % K;
        float w = (nrow < Nl) ? Wl[(size_t)k * Nl + nrow]
                              : Wr[(size_t)k * Nr + (nrow - Nl)];
        __nv_bfloat16 h = __float2bfloat16(w);
        Bh[i] = h;
        Bl[i] = __float2bfloat16(w - __bfloat162float(h));
    }
    if (i < N) bias[i] = (i < Nl) ? 0.0f : b[i - Nl];
}

// ---- GEMM: C[M x Nld](fp32) = A[M x 128] @ B[Nld x 128]^T + bias -----------
// A, B pre-split bf16 hi/lo. CTA tile 128x128, 8 warps (4M x 2N), warp 32x64.
// 3 passes: Ah*Bh, Al*Bh, Ah*Bl into the same fp32 accumulators.
__global__ void __launch_bounds__(256)
k_gemm_mma(const __nv_bfloat16* __restrict__ Ah, const __nv_bfloat16* __restrict__ Al,
           const __nv_bfloat16* __restrict__ Bh, const __nv_bfloat16* __restrict__ Bl,
           const float* __restrict__ bias, float* __restrict__ C, int M, int Nld) {
    extern __shared__ __nv_bfloat16 sm[];
    __nv_bfloat16* sAh = sm;
    __nv_bfloat16* sAl = sm + 128 * SM_STRIDE;
    __nv_bfloat16* sBh = sm + 2 * 128 * SM_STRIDE;
    __nv_bfloat16* sBl = sm + 3 * 128 * SM_STRIDE;

    int tid = threadIdx.x, lane = tid & 31, wid = tid >> 5;
    int row0 = blockIdx.x * 128, col0 = blockIdx.y * 128;

    // load tiles (each 128x128 bf16, uint4 = 8 bf16, 16 uint4/row)
#pragma unroll
    for (int t = 0; t < 8; t++) {
        int lin = t * 256 + tid;
        int r = lin >> 4;
        int c8 = (lin & 15) * 8;
        bool v = (row0 + r) < M;
        uint4 zh = make_uint4(0, 0, 0, 0);
        uint4 h = v ? __ldg((const uint4*)(Ah + (size_t)(row0 + r) * 128 + c8)) : zh;
        uint4 l = v ? __ldg((const uint4*)(Al + (size_t)(row0 + r) * 128 + c8)) : zh;
        *(uint4*)(sAh + r * SM_STRIDE + c8) = h;
        *(uint4*)(sAl + r * SM_STRIDE + c8) = l;
        *(uint4*)(sBh + r * SM_STRIDE + c8) = __ldg((const uint4*)(Bh + (size_t)(col0 + r) * 128 + c8));
        *(uint4*)(sBl + r * SM_STRIDE + c8) = __ldg((const uint4*)(Bl + (size_t)(col0 + r) * 128 + c8));
    }
    __syncthreads();

    int wm = wid & 3;        // 4 M chunks of 32
    int wn = wid >> 2;       // 2 N chunks of 64
    float acc[2][8][4];
#pragma unroll
    for (int i = 0; i < 2; i++)
#pragma unroll
        for (int j = 0; j < 8; j++)
#pragma unroll
            for (int q = 0; q < 4; q++) acc[i][j][q] = 0.f;

    int a_mr = wm * 32 + (lane & 15);          // + i*16
    int a_ko = (lane >> 4) << 3;               // + k
    int b_nr = wn * 64 + (lane & 7) + ((lane >> 4) << 3);   // + j*16
    int b_ko = lane & 8;                       // + k

#pragma unroll
    for (int p = 0; p < 3; p++) {
        const __nv_bfloat16* As = (p == 1) ? sAl : sAh;
        const __nv_bfloat16* Bs = (p == 2) ? sBl : sBh;
#pragma unroll
        for (int ks = 0; ks < 8; ks++) {
            int k = ks * 16;
            uint32_t a[2][4];
#pragma unroll
            for (int i = 0; i < 2; i++)
                ldsm_x4(smem_u32(As + (a_mr + i * 16) * SM_STRIDE + k + a_ko),
                        a[i][0], a[i][1], a[i][2], a[i][3]);
            uint32_t b[8][2];
#pragma unroll
            for (int j = 0; j < 4; j++)
                ldsm_x4(smem_u32(Bs + (b_nr + j * 16) * SM_STRIDE + k + b_ko),
                        b[2 * j][0], b[2 * j][1], b[2 * j + 1][0], b[2 * j + 1][1]);
#pragma unroll
            for (int i = 0; i < 2; i++)
#pragma unroll
                for (int j = 0; j < 8; j++)
                    mma_bf16(acc[i][j], a[i], b[j][0], b[j][1]);
        }
    }

    // epilogue
    int mrow = row0 + wm * 32 + (lane >> 2);
#pragma unroll
    for (int i = 0; i < 2; i++) {
        int m0 = mrow + i * 16;
#pragma unroll
        for (int j = 0; j < 8; j++) {
            int n = col0 + wn * 64 + j * 8 + 2 * (lane & 3);
            float bs0 = __ldg(bias + n), bs1 = __ldg(bias + n + 1);
            if (m0 < M)
                *(float2*)(C + (size_t)m0 * Nld + n) =
                    make_float2(acc[i][j][0] + bs0, acc[i][j][1] + bs1);
            if (m0 + 8 < M)
                *(float2*)(C + (size_t)(m0 + 8) * Nld + n) =
                    make_float2(acc[i][j][2] + bs0, acc[i][j][3] + bs1);
        }
    }
}

// ---- aggregation -----------------------------------------------------------
// layer 1: h = relu(agg(u)*invdeg + v), emitted as split bf16 (hi/lo)
__global__ void k_agg_h(const float* __restrict__ U, const float* __restrict__ V,
                        __nv_bfloat16* __restrict__ Hh, __nv_bfloat16* __restrict__ Hl,
                        int n) {
    int warp = blockIdx.x * (blockDim.x >> 5) + (threadIdx.x >> 5);
    int lane = threadIdx.x & 31;
    if (warp >= n) return;
    int beg = g_rowptr[warp], end = g_rowptr[warp + 1];
    const float* Ub = U + lane * 4;
    float id = g_invdeg[warp];

    float4 a = make_float4(0.f, 0.f, 0.f, 0.f);
    int e = beg;
    for (; e + 2 <= end; e += 2) {
        int s0 = g_col[e], s1 = g_col[e + 1];
        float4 v0 = *(const float4*)(Ub + (size_t)s0 * 256);
        float4 v1 = *(const float4*)(Ub + (size_t)s1 * 256);
        a.x += v0.x + v1.x; a.y += v0.y + v1.y;
        a.z += v0.z + v1.z; a.w += v0.w + v1.w;
    }
    if (e < end) {
        int s = g_col[e];
        float4 v = *(const float4*)(Ub + (size_t)s * 256);
        a.x += v.x; a.y += v.y; a.z += v.z; a.w += v.w;
    }
    float4 vv = *(const float4*)(V + (size_t)warp * 256 + lane * 4);
    float4 o;
    o.x = fmaxf(a.x * id + vv.x, 0.f);
    o.y = fmaxf(a.y * id + vv.y, 0.f);
    o.z = fmaxf(a.z * id + vv.z, 0.f);
    o.w = fmaxf(a.w * id + vv.w, 0.f);
    uint2 hv, lv;
    split4(o, hv, lv);
    *(uint2*)(Hh + (size_t)warp * 128 + lane * 4) = hv;
    *(uint2*)(Hl + (size_t)warp * 128 + lane * 4) = lv;
}

// layer 2: out = agg(p)*invdeg + q  (fp32 output, 64 cols)
__global__ void k_agg_out(const float* __restrict__ P, const float* __restrict__ Q,
                          float* __restrict__ O, int n) {
    int warp = blockIdx.x * (blockDim.x >> 5) + (threadIdx.x >> 5);
    int lane = threadIdx.x & 31;
    if (warp >= n) return;
    int beg = g_rowptr[warp], end = g_rowptr[warp + 1];
    const float* Pb = P + lane * 2;
    float id = g_invdeg[warp];

    float2 a = make_float2(0.f, 0.f);
    int e = beg;
    for (; e + 2 <= end; e += 2) {
        int s0 = g_col[e], s1 = g_col[e + 1];
        float2 v0 = *(const float2*)(Pb + (size_t)s0 * 128);
        float2 v1 = *(const float2*)(Pb + (size_t)s1 * 128);
        a.x += v0.x + v1.x; a.y += v0.y + v1.y;
    }
    if (e < end) {
        int s = g_col[e];
        float2 v = *(const float2*)(Pb + (size_t)s * 128);
        a.x += v.x; a.y += v.y;
    }
    float2 q = *(const float2*)(Q + (size_t)warp * 128 + lane * 2);
    *(float2*)(O + (size_t)warp * 64 + lane * 2) =
        make_float2(a.x * id + q.x, a.y * id + q.y);
}

// ---- launch ----------------------------------------------------------------

extern "C" void kernel_launch(void* const* d_in, const int* in_sizes, int n_in,
                              void* d_out, int out_size) {
    const float* x   = (const float*)d_in[0];
    const void*  edg = d_in[1];
    const float* W1l = (const float*)d_in[2];
    const float* b1  = (const float*)d_in[3];
    const float* W1r = (const float*)d_in[4];
    const float* W2l = (const float*)d_in[5];
    const float* b2  = (const float*)d_in[6];
    const float* W2r = (const float*)d_in[7];

    int n    = in_sizes[0] / 128;   // 100000
    int twoE = in_sizes[1];         // 3,200,000
    int E    = twoE / 2;

    float *UV, *PQ, *bs1, *bs2;
    __nv_bfloat16 *Xh, *Xl, *Hh, *Hl, *B1h, *B1l, *B2h, *B2l;
    cudaGetSymbolAddress((void**)&UV,  g_UV);
    cudaGetSymbolAddress((void**)&PQ,  g_PQ);
    cudaGetSymbolAddress((void**)&Xh,  g_Xh);
    cudaGetSymbolAddress((void**)&Xl,  g_Xl);
    cudaGetSymbolAddress((void**)&Hh,  g_Hh);
    cudaGetSymbolAddress((void**)&Hl,  g_Hl);
    cudaGetSymbolAddress((void**)&B1h, g_B1h);
    cudaGetSymbolAddress((void**)&B1l, g_B1l);
    cudaGetSymbolAddress((void**)&B2h, g_B2h);
    cudaGetSymbolAddress((void**)&B2l, g_B2l);
    cudaGetSymbolAddress((void**)&bs1, g_bias1);
    cudaGetSymbolAddress((void**)&bs2, g_bias2);

    // CSR build
    k_zero<<<(n + 255) / 256, 256>>>(n);
    k_detect<<<16, 256>>>((const unsigned int*)edg);
    k_convert<<<(twoE + 255) / 256, 256>>>(edg, twoE);
    k_hist<<<(E + 255) / 256, 256>>>(E);
    int nb = (n + SCAN_B - 1) / SCAN_B;
    k_scan1<<<nb, SCAN_B>>>(n);
    k_scan2<<<1, 128>>>(nb);
    k_scan3<<<(n + 255) / 256, 256>>>(n, E);
    k_fill<<<(E + 255) / 256, 256>>>(E);

    // operand prep (bf16 splits)
    int total4 = n * 32;
    k_prepA<<<(total4 + 255) / 256, 256>>>(x, Xh, Xl, total4);
    k_prepB<<<(256 * 128 + 255) / 256, 256>>>(W1l, W1r, b1, B1h, B1l, bs1, 128, 128, 128);
    k_prepB<<<(128 * 128 + 255) / 256, 256>>>(W2l, W2r, b2, B2h, B2l, bs2, 128, 64, 64);

    int gx = (n + 127) / 128;       // 782
    constexpr int SMEM = 4 * 128 * SM_STRIDE * 2;   // 139264 B
    static bool attr_set = false;
    if (!attr_set) {
        cudaFuncSetAttribute(k_gemm_mma, cudaFuncAttributeMaxDynamicSharedMemorySize, SMEM);
        attr_set = true;
    }

    // layer 1: [u|v] = x @ [W1l|W1r] (+b1 on v);  h = relu(agg(u)*invdeg + v)
    k_gemm_mma<<<dim3(gx, 2), 256, SMEM>>>(Xh, Xl, B1h, B1l, bs1, UV, n, 256);
    k_agg_h<<<(n + 7) / 8, 256>>>(UV, UV + 128, Hh, Hl, n);

    // layer 2: [p|q] = h @ [W2l|W2r] (+b2 on q);  out = agg(p)*invdeg + q
    k_gemm_mma<<<dim3(gx, 1), 256, SMEM>>>(Hh, Hl, B2h, B2l, bs2, PQ, n, 128);
    k_agg_out<<<(n + 7) / 8, 256>>>(PQ, PQ + 64, (float*)d_out, n);
}

// round 4
// speedup vs baseline: 1.8403x; 1.0664x over previous
#include <cuda_runtime.h>
#include <cuda_bf16.h>
#include <cuda_fp16.h>
#include <cstdint>

// ---------------------------------------------------------------------------
// SAGEConvolution via projection-first form:
//   h   = relu(agg(x @ W1_l) + x @ W1_r + b1)
//   out = agg(h @ W2_l) + h @ W2_r + b2
// GEMMs: warp-level bf16 mma.sync with 2-term error-compensated split
//   D = Ah*Bh + Al*Bh + Ah*Bl (fp32 accum; dropped Al*Bl ~ 2^-18)
// Gathered operands (u = x@W1_l, p = h@W2_l) stored fp16 -> halves L2 traffic.
// agg via CSR gather-sum (one warp per destination node, 4-way unrolled).
// ---------------------------------------------------------------------------

#define N_NODES   100000
#define N_EDGES_M 1600000
#define SCAN_B    1024
#define NB_MAX    128
#define SM_STRIDE 136   // bf16 elements per smem row (128 + 8 pad)

// ---- scratch (device globals; no allocation allowed) ----
__device__ __half g_U[(size_t)N_NODES * 128];   // u = x@W1l (fp16, gathered)
__device__ float  g_V[(size_t)N_NODES * 128];   // v = x@W1r + b1 (fp32)
__device__ __half g_P[(size_t)N_NODES * 64];    // p = h@W2l (fp16, gathered)
__device__ float  g_Q[(size_t)N_NODES * 64];    // q = h@W2r + b2 (fp32)
__device__ __nv_bfloat16 g_Hh[(size_t)N_NODES * 128];
__device__ __nv_bfloat16 g_Hl[(size_t)N_NODES * 128];
__device__ int   g_deg[N_NODES];
__device__ int   g_cur[N_NODES];
__device__ int   g_rowptr[N_NODES + 1];
__device__ int   g_bsum[NB_MAX];
__device__ int   g_boff[NB_MAX];
__device__ float g_invdeg[N_NODES];
__device__ int   g_col[N_EDGES_M];
__device__ int   g_flag;                        // 1 => edge buffer is int32
__device__ __nv_bfloat16 g_B1h[256 * 128];
__device__ __nv_bfloat16 g_B1l[256 * 128];
__device__ __nv_bfloat16 g_B2h[128 * 128];
__device__ __nv_bfloat16 g_B2l[128 * 128];
__device__ float g_bias1[256];
__device__ float g_bias2[128];

// ============================ helpers =======================================

__device__ __forceinline__ uint32_t smem_u32(const void* p) {
    uint32_t a;
    asm("{ .reg .u64 t; cvta.to.shared.u64 t, %1; cvt.u32.u64 %0, t; }"
        : "=r"(a) : "l"(p));
    return a;
}

__device__ __forceinline__ void ldsm_x4(uint32_t addr, uint32_t& r0, uint32_t& r1,
                                        uint32_t& r2, uint32_t& r3) {
    asm volatile("ldmatrix.sync.aligned.m8n8.x4.shared.b16 {%0,%1,%2,%3}, [%4];"
                 : "=r"(r0), "=r"(r1), "=r"(r2), "=r"(r3) : "r"(addr));
}

__device__ __forceinline__ void mma_bf16(float* c, const uint32_t* a,
                                         uint32_t b0, uint32_t b1) {
    asm volatile(
        "mma.sync.aligned.m16n8k16.row.col.f32.bf16.bf16.f32 "
        "{%0,%1,%2,%3}, {%4,%5,%6,%7}, {%8,%9}, {%0,%1,%2,%3};"
        : "+f"(c[0]), "+f"(c[1]), "+f"(c[2]), "+f"(c[3])
        : "r"(a[0]), "r"(a[1]), "r"(a[2]), "r"(a[3]), "r"(b0), "r"(b1));
}

__device__ __forceinline__ void split4(float4 v, uint2& hv, uint2& lv) {
    __nv_bfloat162 h01 = __float22bfloat162_rn(make_float2(v.x, v.y));
    __nv_bfloat162 h23 = __float22bfloat162_rn(make_float2(v.z, v.w));
    float2 f01 = __bfloat1622float2(h01);
    float2 f23 = __bfloat1622float2(h23);
    __nv_bfloat162 l01 = __float22bfloat162_rn(make_float2(v.x - f01.x, v.y - f01.y));
    __nv_bfloat162 l23 = __float22bfloat162_rn(make_float2(v.z - f23.x, v.w - f23.y));
    hv.x = *(uint32_t*)&h01; hv.y = *(uint32_t*)&h23;
    lv.x = *(uint32_t*)&l01; lv.y = *(uint32_t*)&l23;
}

// ---- setup kernels --------------------------------------------------------

__global__ void k_zero(int n) {
    int i = blockIdx.x * blockDim.x + threadIdx.x;
    if (i < n) { g_deg[i] = 0; g_cur[i] = 0; }
    if (i == 0) g_flag = 0;
}

__global__ void k_detect(const unsigned int* __restrict__ w) {
    int i = blockIdx.x * blockDim.x + threadIdx.x;
    if (i < 4096 && w[2 * i + 1] != 0u) g_flag = 1;
}

__device__ __forceinline__ int edge_at(const void* ep, int idx) {
    return g_flag ? ((const int*)ep)[idx]
                  : (int)(((const long long*)ep)[idx]);
}

__global__ void k_hist(const void* __restrict__ ep, int E) {
    int i = blockIdx.x * blockDim.x + threadIdx.x;
    if (i < E) atomicAdd(&g_deg[edge_at(ep, E + i)], 1);
}

__global__ void k_scan1(int n) {
    __shared__ int sm[SCAN_B];
    int tid = threadIdx.x;
    int i = blockIdx.x * SCAN_B + tid;
    int v = (i < n) ? g_deg[i] : 0;
    sm[tid] = v;
    __syncthreads();
    for (int off = 1; off < SCAN_B; off <<= 1) {
        int t = (tid >= off) ? sm[tid - off] : 0;
        __syncthreads();
        sm[tid] += t;
        __syncthreads();
    }
    if (i < n) g_rowptr[i] = sm[tid];
    if (tid == SCAN_B - 1) g_bsum[blockIdx.x] = sm[tid];
}

__global__ void k_scan2(int nb) {
    __shared__ int sm[128];
    int tid = threadIdx.x;
    int v = (tid < nb) ? g_bsum[tid] : 0;
    sm[tid] = v;
    __syncthreads();
    for (int off = 1; off < 128; off <<= 1) {
        int t = (tid >= off) ? sm[tid - off] : 0;
        __syncthreads();
        sm[tid] += t;
        __syncthreads();
    }
    g_boff[tid] = sm[tid] - v;
}

__global__ void k_scan3(int n, int E) {
    int i = blockIdx.x * blockDim.x + threadIdx.x;
    if (i >= n) return;
    int d = g_deg[i];
    int ex = g_rowptr[i] - d + g_boff[i >> 10];
    g_rowptr[i] = ex;
    g_invdeg[i] = 1.0f / (float)max(d, 1);
    if (i == n - 1) g_rowptr[n] = E;
}

__global__ void k_fill(const void* __restrict__ ep, int E) {
    int i = blockIdx.x * blockDim.x + threadIdx.x;
    if (i >= E) return;
    int d = edge_at(ep, E + i);
    int pos = atomicAdd(&g_cur[d], 1);
    g_col[g_rowptr[d] + pos] = edge_at(ep, i);
}

// Build split-bf16 B = [Wl | Wr]^T as [N][K] rows, and bias [0.. | b]
__global__ void k_prepB(const float* __restrict__ Wl, const float* __restrict__ Wr,
                        const float* __restrict__ b,
                        __nv_bfloat16* __restrict__ Bh, __nv_bfloat16* __restrict__ Bl,
                        float* __restrict__ bias, int K, int Nl, int Nr) {
    int N = Nl + Nr;
    int i = blockIdx.x * blockDim.x + threadIdx.x;
    if (i < N * K) {
        int nrow = i / K, k = i % K;
        float w = (nrow < Nl) ? Wl[(size_t)k * Nl + nrow]
                              : Wr[(size_t)k * Nr + (nrow - Nl)];
        __nv_bfloat16 h = __float2bfloat16(w);
        Bh[i] = h;
        Bl[i] = __float2bfloat16(w - __bfloat162float(h));
    }
    if (i < N) bias[i] = (i < Nl) ? 0.0f : b[i - Nl];
}

// ---- GEMM core: 128x128 CTA tile, 8 warps (4M x 2N), warp 32x64 -----------
// A in sAh/sAl, B in sBh/sBl (SM_STRIDE rows). Result in acc.
struct MmaCtx {
    float acc[2][8][4];
    int a_mr, a_ko, b_nr, b_ko, wm, wn, lane;
};

__device__ __forceinline__ void mma_core(MmaCtx& cx,
        const __nv_bfloat16* sAh, const __nv_bfloat16* sAl,
        const __nv_bfloat16* sBh, const __nv_bfloat16* sBl) {
#pragma unroll
    for (int p = 0; p < 3; p++) {
        const __nv_bfloat16* As = (p == 1) ? sAl : sAh;
        const __nv_bfloat16* Bs = (p == 2) ? sBl : sBh;
#pragma unroll
        for (int ks = 0; ks < 8; ks++) {
            int k = ks * 16;
            uint32_t a[2][4];
#pragma unroll
            for (int i = 0; i < 2; i++)
                ldsm_x4(smem_u32(As + (cx.a_mr + i * 16) * SM_STRIDE + k + cx.a_ko),
                        a[i][0], a[i][1], a[i][2], a[i][3]);
            uint32_t b[8][2];
#pragma unroll
            for (int j = 0; j < 4; j++)
                ldsm_x4(smem_u32(Bs + (cx.b_nr + j * 16) * SM_STRIDE + k + cx.b_ko),
                        b[2 * j][0], b[2 * j][1], b[2 * j + 1][0], b[2 * j + 1][1]);
#pragma unroll
            for (int i = 0; i < 2; i++)
#pragma unroll
                for (int j = 0; j < 8; j++)
                    mma_bf16(cx.acc[i][j], a[i], b[j][0], b[j][1]);
        }
    }
}

__device__ __forceinline__ void mma_init(MmaCtx& cx, int tid) {
    int lane = tid & 31, wid = tid >> 5;
    cx.lane = lane;
    cx.wm = wid & 3;
    cx.wn = wid >> 2;
#pragma unroll
    for (int i = 0; i < 2; i++)
#pragma unroll
        for (int j = 0; j < 8; j++)
#pragma unroll
            for (int q = 0; q < 4; q++) cx.acc[i][j][q] = 0.f;
    cx.a_mr = cx.wm * 32 + (lane & 15);
    cx.a_ko = (lane >> 4) << 3;
    cx.b_nr = cx.wn * 64 + (lane & 7) + ((lane >> 4) << 3);
    cx.b_ko = lane & 8;
}

// GEMM1: A = x (fp32, split in-kernel), B pre-split; yb=0 -> u (fp16),
// yb=1 -> v (fp32). M rows, K=N=128 per block tile.
__global__ void __launch_bounds__(256)
k_gemm1(const float* __restrict__ X,
        const __nv_bfloat16* __restrict__ Bh, const __nv_bfloat16* __restrict__ Bl,
        const float* __restrict__ bias,
        __half* __restrict__ U, float* __restrict__ V, int M) {
    extern __shared__ __nv_bfloat16 sm[];
    __nv_bfloat16* sAh = sm;
    __nv_bfloat16* sAl = sm + 128 * SM_STRIDE;
    __nv_bfloat16* sBh = sm + 2 * 128 * SM_STRIDE;
    __nv_bfloat16* sBl = sm + 3 * 128 * SM_STRIDE;

    int tid = threadIdx.x;
    int row0 = blockIdx.x * 128, col0 = blockIdx.y * 128;

    // A: load fp32, split to bf16 hi/lo in smem. 2 threads per row.
    {
        int r = tid >> 1, hf = tid & 1;
        bool v = (row0 + r) < M;
        const float4* Ar = (const float4*)(X + (size_t)(row0 + r) * 128) + hf * 16;
#pragma unroll
        for (int i = 0; i < 16; i++) {
            float4 x4 = v ? __ldg(Ar + i) : make_float4(0.f, 0.f, 0.f, 0.f);
            uint2 hv, lv;
            split4(x4, hv, lv);
            int c = hf * 64 + i * 4;
            *(uint2*)(sAh + r * SM_STRIDE + c) = hv;
            *(uint2*)(sAl + r * SM_STRIDE + c) = lv;
        }
    }
    // B tiles (bf16 pre-split)
#pragma unroll
    for (int t = 0; t < 8; t++) {
        int lin = t * 256 + tid;
        int r = lin >> 4, c8 = (lin & 15) * 8;
        *(uint4*)(sBh + r * SM_STRIDE + c8) = __ldg((const uint4*)(Bh + (size_t)(col0 + r) * 128 + c8));
        *(uint4*)(sBl + r * SM_STRIDE + c8) = __ldg((const uint4*)(Bl + (size_t)(col0 + r) * 128 + c8));
    }
    __syncthreads();

    MmaCtx cx;
    mma_init(cx, tid);
    mma_core(cx, sAh, sAl, sBh, sBl);

    int mrow = row0 + cx.wm * 32 + (cx.lane >> 2);
#pragma unroll
    for (int i = 0; i < 2; i++) {
        int m0 = mrow + i * 16;
#pragma unroll
        for (int j = 0; j < 8; j++) {
            int n = col0 + cx.wn * 64 + j * 8 + 2 * (cx.lane & 3);
            float bs0 = __ldg(bias + n), bs1 = __ldg(bias + n + 1);
            float c00 = cx.acc[i][j][0] + bs0, c01 = cx.acc[i][j][1] + bs1;
            float c10 = cx.acc[i][j][2] + bs0, c11 = cx.acc[i][j][3] + bs1;
            if (blockIdx.y == 0) {   // u -> fp16
                __half2 h0 = __floats2half2_rn(c00, c01);
                __half2 h1 = __floats2half2_rn(c10, c11);
                if (m0 < M)     *(__half2*)(U + (size_t)m0 * 128 + n) = h0;
                if (m0 + 8 < M) *(__half2*)(U + (size_t)(m0 + 8) * 128 + n) = h1;
            } else {                 // v -> fp32
                int nv = n - 128;
                if (m0 < M)     *(float2*)(V + (size_t)m0 * 128 + nv) = make_float2(c00, c01);
                if (m0 + 8 < M) *(float2*)(V + (size_t)(m0 + 8) * 128 + nv) = make_float2(c10, c11);
            }
        }
    }
}

// GEMM2: A = H (bf16 pre-split), single 128-col tile: cols<64 -> p (fp16),
// cols>=64 -> q (fp32).
__global__ void __launch_bounds__(256)
k_gemm2(const __nv_bfloat16* __restrict__ Ah, const __nv_bfloat16* __restrict__ Al,
        const __nv_bfloat16* __restrict__ Bh, const __nv_bfloat16* __restrict__ Bl,
        const float* __restrict__ bias,
        __half* __restrict__ P, float* __restrict__ Q, int M) {
    extern __shared__ __nv_bfloat16 sm[];
    __nv_bfloat16* sAh = sm;
    __nv_bfloat16* sAl = sm + 128 * SM_STRIDE;
    __nv_bfloat16* sBh = sm + 2 * 128 * SM_STRIDE;
    __nv_bfloat16* sBl = sm + 3 * 128 * SM_STRIDE;

    int tid = threadIdx.x;
    int row0 = blockIdx.x * 128;

#pragma unroll
    for (int t = 0; t < 8; t++) {
        int lin = t * 256 + tid;
        int r = lin >> 4, c8 = (lin & 15) * 8;
        bool v = (row0 + r) < M;
        uint4 z = make_uint4(0, 0, 0, 0);
        *(uint4*)(sAh + r * SM_STRIDE + c8) = v ? __ldg((const uint4*)(Ah + (size_t)(row0 + r) * 128 + c8)) : z;
        *(uint4*)(sAl + r * SM_STRIDE + c8) = v ? __ldg((const uint4*)(Al + (size_t)(row0 + r) * 128 + c8)) : z;
        *(uint4*)(sBh + r * SM_STRIDE + c8) = __ldg((const uint4*)(Bh + (size_t)r * 128 + c8));
        *(uint4*)(sBl + r * SM_STRIDE + c8) = __ldg((const uint4*)(Bl + (size_t)r * 128 + c8));
    }
    __syncthreads();

    MmaCtx cx;
    mma_init(cx, tid);
    mma_core(cx, sAh, sAl, sBh, sBl);

    int mrow = row0 + cx.wm * 32 + (cx.lane >> 2);
#pragma unroll
    for (int i = 0; i < 2; i++) {
        int m0 = mrow + i * 16;
#pragma unroll
        for (int j = 0; j < 8; j++) {
            int n = cx.wn * 64 + j * 8 + 2 * (cx.lane & 3);
            float bs0 = __ldg(bias + n), bs1 = __ldg(bias + n + 1);
            float c00 = cx.acc[i][j][0] + bs0, c01 = cx.acc[i][j][1] + bs1;
            float c10 = cx.acc[i][j][2] + bs0, c11 = cx.acc[i][j][3] + bs1;
            if (n < 64) {            // p -> fp16
                __half2 h0 = __floats2half2_rn(c00, c01);
                __half2 h1 = __floats2half2_rn(c10, c11);
                if (m0 < M)     *(__half2*)(P + (size_t)m0 * 64 + n) = h0;
                if (m0 + 8 < M) *(__half2*)(P + (size_t)(m0 + 8) * 64 + n) = h1;
            } else {                 // q -> fp32
                int nq = n - 64;
                if (m0 < M)     *(float2*)(Q + (size_t)m0 * 64 + nq) = make_float2(c00, c01);
                if (m0 + 8 < M) *(float2*)(Q + (size_t)(m0 + 8) * 64 + nq) = make_float2(c10, c11);
            }
        }
    }
}

// ---- aggregation -----------------------------------------------------------
// layer 1: h = relu(agg(u)*invdeg + v); u fp16 (256B/row), h -> bf16 hi/lo
__global__ void k_agg_h(const __half* __restrict__ U, const float* __restrict__ V,
                        __nv_bfloat16* __restrict__ Hh, __nv_bfloat16* __restrict__ Hl,
                        int n) {
    int warp = blockIdx.x * (blockDim.x >> 5) + (threadIdx.x >> 5);
    int lane = threadIdx.x & 31;
    if (warp >= n) return;
    int beg = g_rowptr[warp], end = g_rowptr[warp + 1];
    const __half* Ub = U + lane * 4;
    float id = g_invdeg[warp];

    float4 a = make_float4(0.f, 0.f, 0.f, 0.f);
    int e = beg;
    for (; e + 4 <= end; e += 4) {
        int s0 = g_col[e], s1 = g_col[e + 1], s2 = g_col[e + 2], s3 = g_col[e + 3];
        uint2 w0 = *(const uint2*)(Ub + (size_t)s0 * 128);
        uint2 w1 = *(const uint2*)(Ub + (size_t)s1 * 128);
        uint2 w2 = *(const uint2*)(Ub + (size_t)s2 * 128);
        uint2 w3 = *(const uint2*)(Ub + (size_t)s3 * 128);
#pragma unroll
        for (int q = 0; q < 4; q++) {
            uint2 w = (q == 0) ? w0 : (q == 1) ? w1 : (q == 2) ? w2 : w3;
            float2 f0 = __half22float2(*(const __half2*)&w.x);
            float2 f1 = __half22float2(*(const __half2*)&w.y);
            a.x += f0.x; a.y += f0.y; a.z += f1.x; a.w += f1.y;
        }
    }
    for (; e < end; e++) {
        int s = g_col[e];
        uint2 w = *(const uint2*)(Ub + (size_t)s * 128);
        float2 f0 = __half22float2(*(const __half2*)&w.x);
        float2 f1 = __half22float2(*(const __half2*)&w.y);
        a.x += f0.x; a.y += f0.y; a.z += f1.x; a.w += f1.y;
    }
    float4 vv = *(const float4*)(V + (size_t)warp * 128 + lane * 4);
    float4 o;
    o.x = fmaxf(a.x * id + vv.x, 0.f);
    o.y = fmaxf(a.y * id + vv.y, 0.f);
    o.z = fmaxf(a.z * id + vv.z, 0.f);
    o.w = fmaxf(a.w * id + vv.w, 0.f);
    uint2 hv, lv;
    split4(o, hv, lv);
    *(uint2*)(Hh + (size_t)warp * 128 + lane * 4) = hv;
    *(uint2*)(Hl + (size_t)warp * 128 + lane * 4) = lv;
}

// layer 2: out = agg(p)*invdeg + q; p fp16 (128B/row), out fp32 (64 cols)
__global__ void k_agg_out(const __half* __restrict__ P, const float* __restrict__ Q,
                          float* __restrict__ O, int n) {
    int warp = blockIdx.x * (blockDim.x >> 5) + (threadIdx.x >> 5);
    int lane = threadIdx.x & 31;
    if (warp >= n) return;
    int beg = g_rowptr[warp], end = g_rowptr[warp + 1];
    const __half* Pb = P + lane * 2;
    float id = g_invdeg[warp];

    float2 a = make_float2(0.f, 0.f);
    int e = beg;
    for (; e + 4 <= end; e += 4) {
        int s0 = g_col[e], s1 = g_col[e + 1], s2 = g_col[e + 2], s3 = g_col[e + 3];
        uint32_t w0 = *(const uint32_t*)(Pb + (size_t)s0 * 64);
        uint32_t w1 = *(const uint32_t*)(Pb + (size_t)s1 * 64);
        uint32_t w2 = *(const uint32_t*)(Pb + (size_t)s2 * 64);
        uint32_t w3 = *(const uint32_t*)(Pb + (size_t)s3 * 64);
#pragma unroll
        for (int q = 0; q < 4; q++) {
            uint32_t w = (q == 0) ? w0 : (q == 1) ? w1 : (q == 2) ? w2 : w3;
            float2 f = __half22float2(*(const __half2*)&w);
            a.x += f.x; a.y += f.y;
        }
    }
    for (; e < end; e++) {
        int s = g_col[e];
        uint32_t w = *(const uint32_t*)(Pb + (size_t)s * 64);
        float2 f = __half22float2(*(const __half2*)&w);
        a.x += f.x; a.y += f.y;
    }
    float2 q = *(const float2*)(Q + (size_t)warp * 64 + lane * 2);
    *(float2*)(O + (size_t)warp * 64 + lane * 2) =
        make_float2(a.x * id + q.x, a.y * id + q.y);
}

// ---- launch ----------------------------------------------------------------

extern "C" void kernel_launch(void* const* d_in, const int* in_sizes, int n_in,
                              void* d_out, int out_size) {
    const float* x   = (const float*)d_in[0];
    const void*  edg = d_in[1];
    const float* W1l = (const float*)d_in[2];
    const float* b1  = (const float*)d_in[3];
    const float* W1r = (const float*)d_in[4];
    const float* W2l = (const float*)d_in[5];
    const float* b2  = (const float*)d_in[6];
    const float* W2r = (const float*)d_in[7];

    int n    = in_sizes[0] / 128;   // 100000
    int twoE = in_sizes[1];         // 3,200,000
    int E    = twoE / 2;

    float *V, *Q, *bs1, *bs2;
    __half *U, *P;
    __nv_bfloat16 *Hh, *Hl, *B1h, *B1l, *B2h, *B2l;
    cudaGetSymbolAddress((void**)&U,   g_U);
    cudaGetSymbolAddress((void**)&V,   g_V);
    cudaGetSymbolAddress((void**)&P,   g_P);
    cudaGetSymbolAddress((void**)&Q,   g_Q);
    cudaGetSymbolAddress((void**)&Hh,  g_Hh);
    cudaGetSymbolAddress((void**)&Hl,  g_Hl);
    cudaGetSymbolAddress((void**)&B1h, g_B1h);
    cudaGetSymbolAddress((void**)&B1l, g_B1l);
    cudaGetSymbolAddress((void**)&B2h, g_B2h);
    cudaGetSymbolAddress((void**)&B2l, g_B2l);
    cudaGetSymbolAddress((void**)&bs1, g_bias1);
    cudaGetSymbolAddress((void**)&bs2, g_bias2);

    // CSR build (reads raw edge buffer; dtype flag set by k_detect)
    k_zero<<<(n + 255) / 256, 256>>>(n);
    k_detect<<<16, 256>>>((const unsigned int*)edg);
    k_hist<<<(E + 255) / 256, 256>>>(edg, E);
    int nb = (n + SCAN_B - 1) / SCAN_B;
    k_scan1<<<nb, SCAN_B>>>(n);
    k_scan2<<<1, 128>>>(nb);
    k_scan3<<<(n + 255) / 256, 256>>>(n, E);
    k_fill<<<(E + 255) / 256, 256>>>(edg, E);

    // weight prep (transpose + bf16 split + bias concat)
    k_prepB<<<(256 * 128 + 255) / 256, 256>>>(W1l, W1r, b1, B1h, B1l, bs1, 128, 128, 128);
    k_prepB<<<(128 * 128 + 255) / 256, 256>>>(W2l, W2r, b2, B2h, B2l, bs2, 128, 64, 64);

    int gx = (n + 127) / 128;       // 782
    constexpr int SMEM = 4 * 128 * SM_STRIDE * 2;   // 139264 B
    static bool attr_set = false;
    if (!attr_set) {
        cudaFuncSetAttribute(k_gemm1, cudaFuncAttributeMaxDynamicSharedMemorySize, SMEM);
        cudaFuncSetAttribute(k_gemm2, cudaFuncAttributeMaxDynamicSharedMemorySize, SMEM);
        attr_set = true;
    }

    // layer 1
    k_gemm1<<<dim3(gx, 2), 256, SMEM>>>(x, B1h, B1l, bs1, U, V, n);
    k_agg_h<<<(n + 7) / 8, 256>>>(U, V, Hh, Hl, n);

    // layer 2
    k_gemm2<<<gx, 256, SMEM>>>(Hh, Hl, B2h, B2l, bs2, P, Q, n);
    k_agg_out<<<(n + 7) / 8, 256>>>(P, Q, (float*)d_out, n);
}

// round 5
// speedup vs baseline: 1.9120x; 1.0390x over previous
#include <cuda_runtime.h>
#include <cuda_bf16.h>
#include <cuda_fp16.h>
#include <cstdint>

// ---------------------------------------------------------------------------
// SAGEConvolution via projection-first form:
//   h   = relu(agg(x @ W1_l) + x @ W1_r + b1)
//   out = agg(h @ W2_l) + h @ W2_r + b2
// GEMMs: warp-level bf16 mma.sync with 2-term error-compensated split.
// Gathered operands (u, p) in fp16. CSR build overlapped with GEMM1 via a
// second stream inside the captured graph (fork/join with events).
// ---------------------------------------------------------------------------

#define N_NODES   100000
#define N_EDGES_M 1600000
#define SCAN_B    1024
#define NB_MAX    128
#define SM_STRIDE 136   // bf16 elements per smem row (128 + 8 pad)

__device__ __half g_U[(size_t)N_NODES * 128];   // u = x@W1l (fp16, gathered)
__device__ float  g_V[(size_t)N_NODES * 128];   // v = x@W1r + b1 (fp32)
__device__ __half g_P[(size_t)N_NODES * 64];    // p = h@W2l (fp16, gathered)
__device__ float  g_Q[(size_t)N_NODES * 64];    // q = h@W2r + b2 (fp32)
__device__ __nv_bfloat16 g_Hh[(size_t)N_NODES * 128];
__device__ __nv_bfloat16 g_Hl[(size_t)N_NODES * 128];
__device__ int   g_deg[N_NODES];
__device__ int   g_cur[N_NODES];
__device__ int   g_rowptr[N_NODES + 1];
__device__ int   g_bsum[NB_MAX];
__device__ int   g_boff[NB_MAX];
__device__ float g_invdeg[N_NODES];
__device__ int   g_col[N_EDGES_M];
__device__ int   g_flag;                        // 1 => edge buffer is int32
__device__ __nv_bfloat16 g_B1h[256 * 128];
__device__ __nv_bfloat16 g_B1l[256 * 128];
__device__ __nv_bfloat16 g_B2h[128 * 128];
__device__ __nv_bfloat16 g_B2l[128 * 128];
__device__ float g_bias1[256];
__device__ float g_bias2[128];

// ============================ helpers =======================================

__device__ __forceinline__ uint32_t smem_u32(const void* p) {
    uint32_t a;
    asm("{ .reg .u64 t; cvta.to.shared.u64 t, %1; cvt.u32.u64 %0, t; }"
        : "=r"(a) : "l"(p));
    return a;
}

__device__ __forceinline__ void ldsm_x4(uint32_t addr, uint32_t& r0, uint32_t& r1,
                                        uint32_t& r2, uint32_t& r3) {
    asm volatile("ldmatrix.sync.aligned.m8n8.x4.shared.b16 {%0,%1,%2,%3}, [%4];"
                 : "=r"(r0), "=r"(r1), "=r"(r2), "=r"(r3) : "r"(addr));
}

__device__ __forceinline__ void mma_bf16(float* c, const uint32_t* a,
                                         uint32_t b0, uint32_t b1) {
    asm volatile(
        "mma.sync.aligned.m16n8k16.row.col.f32.bf16.bf16.f32 "
        "{%0,%1,%2,%3}, {%4,%5,%6,%7}, {%8,%9}, {%0,%1,%2,%3};"
        : "+f"(c[0]), "+f"(c[1]), "+f"(c[2]), "+f"(c[3])
        : "r"(a[0]), "r"(a[1]), "r"(a[2]), "r"(a[3]), "r"(b0), "r"(b1));
}

__device__ __forceinline__ void split4(float4 v, uint2& hv, uint2& lv) {
    __nv_bfloat162 h01 = __float22bfloat162_rn(make_float2(v.x, v.y));
    __nv_bfloat162 h23 = __float22bfloat162_rn(make_float2(v.z, v.w));
    float2 f01 = __bfloat1622float2(h01);
    float2 f23 = __bfloat1622float2(h23);
    __nv_bfloat162 l01 = __float22bfloat162_rn(make_float2(v.x - f01.x, v.y - f01.y));
    __nv_bfloat162 l23 = __float22bfloat162_rn(make_float2(v.z - f23.x, v.w - f23.y));
    hv.x = *(uint32_t*)&h01; hv.y = *(uint32_t*)&h23;
    lv.x = *(uint32_t*)&l01; lv.y = *(uint32_t*)&l23;
}

// ---- setup kernels --------------------------------------------------------

__global__ void k_zero(int n) {
    int i = blockIdx.x * blockDim.x + threadIdx.x;
    if (i < n) { g_deg[i] = 0; g_cur[i] = 0; }
    if (i == 0) g_flag = 0;
}

__global__ void k_detect(const unsigned int* __restrict__ w) {
    int i = blockIdx.x * blockDim.x + threadIdx.x;
    if (i < 4096 && w[2 * i + 1] != 0u) g_flag = 1;
}

__device__ __forceinline__ int edge_at(const void* ep, int idx) {
    return g_flag ? ((const int*)ep)[idx]
                  : (int)(((const long long*)ep)[idx]);
}

__global__ void k_hist(const void* __restrict__ ep, int E) {
    int i = blockIdx.x * blockDim.x + threadIdx.x;
    if (i < E) atomicAdd(&g_deg[edge_at(ep, E + i)], 1);
}

__global__ void k_scan1(int n) {
    __shared__ int sm[SCAN_B];
    int tid = threadIdx.x;
    int i = blockIdx.x * SCAN_B + tid;
    int v = (i < n) ? g_deg[i] : 0;
    sm[tid] = v;
    __syncthreads();
    for (int off = 1; off < SCAN_B; off <<= 1) {
        int t = (tid >= off) ? sm[tid - off] : 0;
        __syncthreads();
        sm[tid] += t;
        __syncthreads();
    }
    if (i < n) g_rowptr[i] = sm[tid];
    if (tid == SCAN_B - 1) g_bsum[blockIdx.x] = sm[tid];
}

__global__ void k_scan2(int nb) {
    __shared__ int sm[128];
    int tid = threadIdx.x;
    int v = (tid < nb) ? g_bsum[tid] : 0;
    sm[tid] = v;
    __syncthreads();
    for (int off = 1; off < 128; off <<= 1) {
        int t = (tid >= off) ? sm[tid - off] : 0;
        __syncthreads();
        sm[tid] += t;
        __syncthreads();
    }
    g_boff[tid] = sm[tid] - v;
}

__global__ void k_scan3(int n, int E) {
    int i = blockIdx.x * blockDim.x + threadIdx.x;
    if (i >= n) return;
    int d = g_deg[i];
    int ex = g_rowptr[i] - d + g_boff[i >> 10];
    g_rowptr[i] = ex;
    g_invdeg[i] = 1.0f / (float)max(d, 1);
    if (i == n - 1) g_rowptr[n] = E;
}

__global__ void k_fill(const void* __restrict__ ep, int E) {
    int i = blockIdx.x * blockDim.x + threadIdx.x;
    if (i >= E) return;
    int d = edge_at(ep, E + i);
    int pos = atomicAdd(&g_cur[d], 1);
    g_col[g_rowptr[d] + pos] = edge_at(ep, i);
}

// Build split-bf16 B = [Wl | Wr]^T as [N][K] rows, and bias [0.. | b]
__global__ void k_prepB(const float* __restrict__ Wl, const float* __restrict__ Wr,
                        const float* __restrict__ b,
                        __nv_bfloat16* __restrict__ Bh, __nv_bfloat16* __restrict__ Bl,
                        float* __restrict__ bias, int K, int Nl, int Nr) {
    int N = Nl + Nr;
    int i = blockIdx.x * blockDim.x + threadIdx.x;
    if (i < N * K) {
        int nrow = i / K, k = i % K;
        float w = (nrow < Nl) ? Wl[(size_t)k * Nl + nrow]
                              : Wr[(size_t)k * Nr + (nrow - Nl)];
        __nv_bfloat16 h = __float2bfloat16(w);
        Bh[i] = h;
        Bl[i] = __float2bfloat16(w - __bfloat162float(h));
    }
    if (i < N) bias[i] = (i < Nl) ? 0.0f : b[i - Nl];
}

// ---- GEMM core: 128x128 CTA tile, 8 warps (4M x 2N), warp 32x64 -----------
struct MmaCtx {
    float acc[2][8][4];
    int a_mr, a_ko, b_nr, b_ko, wm, wn, lane;
};

__device__ __forceinline__ void mma_core(MmaCtx& cx,
        const __nv_bfloat16* sAh, const __nv_bfloat16* sAl,
        const __nv_bfloat16* sBh, const __nv_bfloat16* sBl) {
#pragma unroll
    for (int p = 0; p < 3; p++) {
        const __nv_bfloat16* As = (p == 1) ? sAl : sAh;
        const __nv_bfloat16* Bs = (p == 2) ? sBl : sBh;
#pragma unroll
        for (int ks = 0; ks < 8; ks++) {
            int k = ks * 16;
            uint32_t a[2][4];
#pragma unroll
            for (int i = 0; i < 2; i++)
                ldsm_x4(smem_u32(As + (cx.a_mr + i * 16) * SM_STRIDE + k + cx.a_ko),
                        a[i][0], a[i][1], a[i][2], a[i][3]);
            uint32_t b[8][2];
#pragma unroll
            for (int j = 0; j < 4; j++)
                ldsm_x4(smem_u32(Bs + (cx.b_nr + j * 16) * SM_STRIDE + k + cx.b_ko),
                        b[2 * j][0], b[2 * j][1], b[2 * j + 1][0], b[2 * j + 1][1]);
#pragma unroll
            for (int i = 0; i < 2; i++)
#pragma unroll
                for (int j = 0; j < 8; j++)
                    mma_bf16(cx.acc[i][j], a[i], b[j][0], b[j][1]);
        }
    }
}

__device__ __forceinline__ void mma_init(MmaCtx& cx, int tid) {
    int lane = tid & 31, wid = tid >> 5;
    cx.lane = lane;
    cx.wm = wid & 3;
    cx.wn = wid >> 2;
#pragma unroll
    for (int i = 0; i < 2; i++)
#pragma unroll
        for (int j = 0; j < 8; j++)
#pragma unroll
            for (int q = 0; q < 4; q++) cx.acc[i][j][q] = 0.f;
    cx.a_mr = cx.wm * 32 + (lane & 15);
    cx.a_ko = (lane >> 4) << 3;
    cx.b_nr = cx.wn * 64 + (lane & 7) + ((lane >> 4) << 3);
    cx.b_ko = lane & 8;
}

// GEMM1: A = x (fp32, split in-kernel); blockIdx.y==0 -> u (fp16), ==1 -> v (fp32)
__global__ void __launch_bounds__(256)
k_gemm1(const float* __restrict__ X,
        const __nv_bfloat16* __restrict__ Bh, const __nv_bfloat16* __restrict__ Bl,
        const float* __restrict__ bias,
        __half* __restrict__ U, float* __restrict__ V, int M) {
    extern __shared__ __nv_bfloat16 sm[];
    __nv_bfloat16* sAh = sm;
    __nv_bfloat16* sAl = sm + 128 * SM_STRIDE;
    __nv_bfloat16* sBh = sm + 2 * 128 * SM_STRIDE;
    __nv_bfloat16* sBl = sm + 3 * 128 * SM_STRIDE;

    int tid = threadIdx.x;
    int row0 = blockIdx.x * 128, col0 = blockIdx.y * 128;

    {
        int r = tid >> 1, hf = tid & 1;
        bool v = (row0 + r) < M;
        const float4* Ar = (const float4*)(X + (size_t)(row0 + r) * 128) + hf * 16;
#pragma unroll
        for (int i = 0; i < 16; i++) {
            float4 x4 = v ? __ldg(Ar + i) : make_float4(0.f, 0.f, 0.f, 0.f);
            uint2 hv, lv;
            split4(x4, hv, lv);
            int c = hf * 64 + i * 4;
            *(uint2*)(sAh + r * SM_STRIDE + c) = hv;
            *(uint2*)(sAl + r * SM_STRIDE + c) = lv;
        }
    }
#pragma unroll
    for (int t = 0; t < 8; t++) {
        int lin = t * 256 + tid;
        int r = lin >> 4, c8 = (lin & 15) * 8;
        *(uint4*)(sBh + r * SM_STRIDE + c8) = __ldg((const uint4*)(Bh + (size_t)(col0 + r) * 128 + c8));
        *(uint4*)(sBl + r * SM_STRIDE + c8) = __ldg((const uint4*)(Bl + (size_t)(col0 + r) * 128 + c8));
    }
    __syncthreads();

    MmaCtx cx;
    mma_init(cx, tid);
    mma_core(cx, sAh, sAl, sBh, sBl);

    int mrow = row0 + cx.wm * 32 + (cx.lane >> 2);
#pragma unroll
    for (int i = 0; i < 2; i++) {
        int m0 = mrow + i * 16;
#pragma unroll
        for (int j = 0; j < 8; j++) {
            int n = col0 + cx.wn * 64 + j * 8 + 2 * (cx.lane & 3);
            float bs0 = __ldg(bias + n), bs1 = __ldg(bias + n + 1);
            float c00 = cx.acc[i][j][0] + bs0, c01 = cx.acc[i][j][1] + bs1;
            float c10 = cx.acc[i][j][2] + bs0, c11 = cx.acc[i][j][3] + bs1;
            if (blockIdx.y == 0) {
                __half2 h0 = __floats2half2_rn(c00, c01);
                __half2 h1 = __floats2half2_rn(c10, c11);
                if (m0 < M)     *(__half2*)(U + (size_t)m0 * 128 + n) = h0;
                if (m0 + 8 < M) *(__half2*)(U + (size_t)(m0 + 8) * 128 + n) = h1;
            } else {
                int nv = n - 128;
                if (m0 < M)     *(float2*)(V + (size_t)m0 * 128 + nv) = make_float2(c00, c01);
                if (m0 + 8 < M) *(float2*)(V + (size_t)(m0 + 8) * 128 + nv) = make_float2(c10, c11);
            }
        }
    }
}

// GEMM2: A = H (bf16 pre-split); cols<64 -> p (fp16), cols>=64 -> q (fp32)
__global__ void __launch_bounds__(256)
k_gemm2(const __nv_bfloat16* __restrict__ Ah, const __nv_bfloat16* __restrict__ Al,
        const __nv_bfloat16* __restrict__ Bh, const __nv_bfloat16* __restrict__ Bl,
        const float* __restrict__ bias,
        __half* __restrict__ P, float* __restrict__ Q, int M) {
    extern __shared__ __nv_bfloat16 sm[];
    __nv_bfloat16* sAh = sm;
    __nv_bfloat16* sAl = sm + 128 * SM_STRIDE;
    __nv_bfloat16* sBh = sm + 2 * 128 * SM_STRIDE;
    __nv_bfloat16* sBl = sm + 3 * 128 * SM_STRIDE;

    int tid = threadIdx.x;
    int row0 = blockIdx.x * 128;

#pragma unroll
    for (int t = 0; t < 8; t++) {
        int lin = t * 256 + tid;
        int r = lin >> 4, c8 = (lin & 15) * 8;
        bool v = (row0 + r) < M;
        uint4 z = make_uint4(0, 0, 0, 0);
        *(uint4*)(sAh + r * SM_STRIDE + c8) = v ? __ldg((const uint4*)(Ah + (size_t)(row0 + r) * 128 + c8)) : z;
        *(uint4*)(sAl + r * SM_STRIDE + c8) = v ? __ldg((const uint4*)(Al + (size_t)(row0 + r) * 128 + c8)) : z;
        *(uint4*)(sBh + r * SM_STRIDE + c8) = __ldg((const uint4*)(Bh + (size_t)r * 128 + c8));
        *(uint4*)(sBl + r * SM_STRIDE + c8) = __ldg((const uint4*)(Bl + (size_t)r * 128 + c8));
    }
    __syncthreads();

    MmaCtx cx;
    mma_init(cx, tid);
    mma_core(cx, sAh, sAl, sBh, sBl);

    int mrow = row0 + cx.wm * 32 + (cx.lane >> 2);
#pragma unroll
    for (int i = 0; i < 2; i++) {
        int m0 = mrow + i * 16;
#pragma unroll
        for (int j = 0; j < 8; j++) {
            int n = cx.wn * 64 + j * 8 + 2 * (cx.lane & 3);
            float bs0 = __ldg(bias + n), bs1 = __ldg(bias + n + 1);
            float c00 = cx.acc[i][j][0] + bs0, c01 = cx.acc[i][j][1] + bs1;
            float c10 = cx.acc[i][j][2] + bs0, c11 = cx.acc[i][j][3] + bs1;
            if (n < 64) {
                __half2 h0 = __floats2half2_rn(c00, c01);
                __half2 h1 = __floats2half2_rn(c10, c11);
                if (m0 < M)     *(__half2*)(P + (size_t)m0 * 64 + n) = h0;
                if (m0 + 8 < M) *(__half2*)(P + (size_t)(m0 + 8) * 64 + n) = h1;
            } else {
                int nq = n - 64;
                if (m0 < M)     *(float2*)(Q + (size_t)m0 * 64 + nq) = make_float2(c00, c01);
                if (m0 + 8 < M) *(float2*)(Q + (size_t)(m0 + 8) * 64 + nq) = make_float2(c10, c11);
            }
        }
    }
}

// ---- aggregation (8-way unrolled gather for deeper MLP) --------------------
__global__ void k_agg_h(const __half* __restrict__ U, const float* __restrict__ V,
                        __nv_bfloat16* __restrict__ Hh, __nv_bfloat16* __restrict__ Hl,
                        int n) {
    int warp = blockIdx.x * (blockDim.x >> 5) + (threadIdx.x >> 5);
    int lane = threadIdx.x & 31;
    if (warp >= n) return;
    int beg = g_rowptr[warp], end = g_rowptr[warp + 1];
    const __half* Ub = U + lane * 4;
    float id = g_invdeg[warp];

    float4 a = make_float4(0.f, 0.f, 0.f, 0.f);
    int e = beg;
    for (; e + 8 <= end; e += 8) {
        uint2 w[8];
#pragma unroll
        for (int q = 0; q < 8; q++)
            w[q] = *(const uint2*)(Ub + (size_t)g_col[e + q] * 128);
#pragma unroll
        for (int q = 0; q < 8; q++) {
            float2 f0 = __half22float2(*(const __half2*)&w[q].x);
            float2 f1 = __half22float2(*(const __half2*)&w[q].y);
            a.x += f0.x; a.y += f0.y; a.z += f1.x; a.w += f1.y;
        }
    }
    for (; e < end; e++) {
        uint2 w = *(const uint2*)(Ub + (size_t)g_col[e] * 128);
        float2 f0 = __half22float2(*(const __half2*)&w.x);
        float2 f1 = __half22float2(*(const __half2*)&w.y);
        a.x += f0.x; a.y += f0.y; a.z += f1.x; a.w += f1.y;
    }
    float4 vv = *(const float4*)(V + (size_t)warp * 128 + lane * 4);
    float4 o;
    o.x = fmaxf(a.x * id + vv.x, 0.f);
    o.y = fmaxf(a.y * id + vv.y, 0.f);
    o.z = fmaxf(a.z * id + vv.z, 0.f);
    o.w = fmaxf(a.w * id + vv.w, 0.f);
    uint2 hv, lv;
    split4(o, hv, lv);
    *(uint2*)(Hh + (size_t)warp * 128 + lane * 4) = hv;
    *(uint2*)(Hl + (size_t)warp * 128 + lane * 4) = lv;
}

__global__ void k_agg_out(const __half* __restrict__ P, const float* __restrict__ Q,
                          float* __restrict__ O, int n) {
    int warp = blockIdx.x * (blockDim.x >> 5) + (threadIdx.x >> 5);
    int lane = threadIdx.x & 31;
    if (warp >= n) return;
    int beg = g_rowptr[warp], end = g_rowptr[warp + 1];
    const __half* Pb = P + lane * 2;
    float id = g_invdeg[warp];

    float2 a = make_float2(0.f, 0.f);
    int e = beg;
    for (; e + 8 <= end; e += 8) {
        uint32_t w[8];
#pragma unroll
        for (int q = 0; q < 8; q++)
            w[q] = *(const uint32_t*)(Pb + (size_t)g_col[e + q] * 64);
#pragma unroll
        for (int q = 0; q < 8; q++) {
            float2 f = __half22float2(*(const __half2*)&w[q]);
            a.x += f.x; a.y += f.y;
        }
    }
    for (; e < end; e++) {
        uint32_t w = *(const uint32_t*)(Pb + (size_t)g_col[e] * 64);
        float2 f = __half22float2(*(const __half2*)&w);
        a.x += f.x; a.y += f.y;
    }
    float2 q = *(const float2*)(Q + (size_t)warp * 64 + lane * 2);
    *(float2*)(O + (size_t)warp * 64 + lane * 2) =
        make_float2(a.x * id + q.x, a.y * id + q.y);
}

// ---- launch ----------------------------------------------------------------

extern "C" void kernel_launch(void* const* d_in, const int* in_sizes, int n_in,
                              void* d_out, int out_size) {
    const float* x   = (const float*)d_in[0];
    const void*  edg = d_in[1];
    const float* W1l = (const float*)d_in[2];
    const float* b1  = (const float*)d_in[3];
    const float* W1r = (const float*)d_in[4];
    const float* W2l = (const float*)d_in[5];
    const float* b2  = (const float*)d_in[6];
    const float* W2r = (const float*)d_in[7];

    int n    = in_sizes[0] / 128;   // 100000
    int twoE = in_sizes[1];         // 3,200,000
    int E    = twoE / 2;

    float *V, *Q, *bs1, *bs2;
    __half *U, *P;
    __nv_bfloat16 *Hh, *Hl, *B1h, *B1l, *B2h, *B2l;
    cudaGetSymbolAddress((void**)&U,   g_U);
    cudaGetSymbolAddress((void**)&V,   g_V);
    cudaGetSymbolAddress((void**)&P,   g_P);
    cudaGetSymbolAddress((void**)&Q,   g_Q);
    cudaGetSymbolAddress((void**)&Hh,  g_Hh);
    cudaGetSymbolAddress((void**)&Hl,  g_Hl);
    cudaGetSymbolAddress((void**)&B1h, g_B1h);
    cudaGetSymbolAddress((void**)&B1l, g_B1l);
    cudaGetSymbolAddress((void**)&B2h, g_B2h);
    cudaGetSymbolAddress((void**)&B2l, g_B2l);
    cudaGetSymbolAddress((void**)&bs1, g_bias1);
    cudaGetSymbolAddress((void**)&bs2, g_bias2);

    static cudaStream_t sB = nullptr;
    static cudaEvent_t evFork = nullptr, evCSR = nullptr;
    constexpr int SMEM = 4 * 128 * SM_STRIDE * 2;   // 139264 B
    if (!sB) {
        cudaStreamCreateWithFlags(&sB, cudaStreamNonBlocking);
        cudaEventCreateWithFlags(&evFork, cudaEventDisableTiming);
        cudaEventCreateWithFlags(&evCSR, cudaEventDisableTiming);
        cudaFuncSetAttribute(k_gemm1, cudaFuncAttributeMaxDynamicSharedMemorySize, SMEM);
        cudaFuncSetAttribute(k_gemm2, cudaFuncAttributeMaxDynamicSharedMemorySize, SMEM);
    }

    // ---- fork: CSR build on side stream sB ----
    cudaEventRecord(evFork, 0);
    cudaStreamWaitEvent(sB, evFork, 0);
    k_zero<<<(n + 255) / 256, 256, 0, sB>>>(n);
    k_detect<<<16, 256, 0, sB>>>((const unsigned int*)edg);
    k_hist<<<(E + 255) / 256, 256, 0, sB>>>(edg, E);
    int nb = (n + SCAN_B - 1) / SCAN_B;
    k_scan1<<<nb, SCAN_B, 0, sB>>>(n);
    k_scan2<<<1, 128, 0, sB>>>(nb);
    k_scan3<<<(n + 255) / 256, 256, 0, sB>>>(n, E);
    k_fill<<<(E + 255) / 256, 256, 0, sB>>>(edg, E);
    cudaEventRecord(evCSR, sB);

    // ---- main stream: weight prep + GEMM1 (independent of CSR) ----
    k_prepB<<<(256 * 128 + 255) / 256, 256>>>(W1l, W1r, b1, B1h, B1l, bs1, 128, 128, 128);
    k_prepB<<<(128 * 128 + 255) / 256, 256>>>(W2l, W2r, b2, B2h, B2l, bs2, 128, 64, 64);

    int gx = (n + 127) / 128;       // 782
    k_gemm1<<<dim3(gx, 2), 256, SMEM>>>(x, B1h, B1l, bs1, U, V, n);

    // ---- join: aggregation needs CSR ----
    cudaStreamWaitEvent(0, evCSR, 0);
    k_agg_h<<<(n + 7) / 8, 256>>>(U, V, Hh, Hl, n);
    k_gemm2<<<gx, 256, SMEM>>>(Hh, Hl, B2h, B2l, bs2, P, Q, n);
    k_agg_out<<<(n + 7) / 8, 256>>>(P, Q, (float*)d_out, n);
}